// round 12
// baseline (speedup 1.0000x reference)
#include <cuda_runtime.h>

// SMFNet: out[i,:] = relu(X@Wf^T)[i,0]*V[i,:] + [i,1]*V[(i+1)%N,:],  V = relu(X@Wg^T)
// Thread-per-row via smem staging: no cross-lane reductions.

#define THREADS 128
#define TILE    128
#define RV      33                      // row stride in float4 (32 + 1 pad)
#define SX_F4   ((TILE + 1) * RV)       // 129 * 33 = 4257 float4
#define SW_F4   128                     // wf0,wf1,wg0,wg1 (32 float4 each)
#define SMEM_BYTES ((SX_F4 + SW_F4) * 16 + (TILE + 2) * 8)

__global__ void __launch_bounds__(THREADS)
smfnet_kernel(const float4* __restrict__ X,
              const float4* __restrict__ Wf,
              const float4* __restrict__ Wg,
              float2* __restrict__ out, int N)
{
    extern __shared__ float4 sm[];
    float4* sX = sm;                         // [TILE+1][RV]
    float4* sW = sm + SX_F4;                 // [128]
    float2* sV = (float2*)(sW + SW_F4);      // [TILE+1]

    const int t = threadIdx.x;
    const long long r0 = (long long)blockIdx.x * TILE;
    const int nrows = (int)min((long long)TILE, (long long)N - r0);

    // Stage weights (2 KB): sW[0..63]=Wf rows 0,1 ; sW[64..127]=Wg rows 0,1
    if (t < 64)  sW[t] = Wf[t];
    else         sW[t] = Wg[t - 64];

    // Stage X rows [r0, r0+nrows) plus wrapped boundary row (r0+nrows)%N.
    const int total = (nrows + 1) * 32;
    for (int idx = t; idx < total; idx += THREADS) {
        const int r = idx >> 5, c = idx & 31;
        long long g = r0 + r;
        if (r == nrows) g = (r0 + nrows) % (long long)N;
        sX[r * RV + c] = X[g * 32 + c];
    }
    __syncthreads();

    float f0 = 0.f, f1 = 0.f;
    if (t < nrows) {
        float g0 = 0.f, g1 = 0.f;
        const float4* xr = sX + t * RV;
        #pragma unroll 4
        for (int j = 0; j < 32; j++) {
            const float4 x = xr[j];
            const float4 a = sW[j];
            const float4 b = sW[32 + j];
            const float4 c = sW[64 + j];
            const float4 d = sW[96 + j];
            f0 = fmaf(x.x, a.x, fmaf(x.y, a.y, fmaf(x.z, a.z, fmaf(x.w, a.w, f0))));
            f1 = fmaf(x.x, b.x, fmaf(x.y, b.y, fmaf(x.z, b.z, fmaf(x.w, b.w, f1))));
            g0 = fmaf(x.x, c.x, fmaf(x.y, c.y, fmaf(x.z, c.z, fmaf(x.w, c.w, g0))));
            g1 = fmaf(x.x, d.x, fmaf(x.y, d.y, fmaf(x.z, d.z, fmaf(x.w, d.w, g1))));
        }
        f0 = fmaxf(f0, 0.f);
        f1 = fmaxf(f1, 0.f);
        sV[t] = make_float2(fmaxf(g0, 0.f), fmaxf(g1, 0.f));

        if (t == nrows - 1) {
            // Wrapped boundary row: only V (Wg dots) needed.
            float e0 = 0.f, e1 = 0.f;
            const float4* xe = sX + nrows * RV;
            #pragma unroll 4
            for (int j = 0; j < 32; j++) {
                const float4 x = xe[j];
                const float4 c = sW[64 + j];
                const float4 d = sW[96 + j];
                e0 = fmaf(x.x, c.x, fmaf(x.y, c.y, fmaf(x.z, c.z, fmaf(x.w, c.w, e0))));
                e1 = fmaf(x.x, d.x, fmaf(x.y, d.y, fmaf(x.z, d.z, fmaf(x.w, d.w, e1))));
            }
            sV[nrows] = make_float2(fmaxf(e0, 0.f), fmaxf(e1, 0.f));
        }
    }
    __syncthreads();

    if (t < nrows) {
        const float2 v  = sV[t];
        const float2 vn = sV[t + 1];
        out[r0 + t] = make_float2(fmaf(f0, v.x, f1 * vn.x),
                                  fmaf(f0, v.y, f1 * vn.y));
    }
}

extern "C" void kernel_launch(void* const* d_in, const int* in_sizes, int n_in,
                              void* d_out, int out_size) {
    const float4* X  = (const float4*)d_in[0];   // [N,128] fp32
    const float4* Wf = (const float4*)d_in[1];   // [2,128] fp32
    const float4* Wg = (const float4*)d_in[2];   // [2,128] fp32
    float2* out = (float2*)d_out;                // [N,2] fp32

    const int N = in_sizes[0] / 128;
    const int grid = (N + TILE - 1) / TILE;

    static bool attr_set = false;
    if (!attr_set) {
        cudaFuncSetAttribute(smfnet_kernel,
                             cudaFuncAttributeMaxDynamicSharedMemorySize,
                             SMEM_BYTES);
        attr_set = true;
    }

    smfnet_kernel<<<grid, THREADS, SMEM_BYTES>>>(X, Wf, Wg, out, N);
}

// round 13
// speedup vs baseline: 1.0268x; 1.0268x over previous
#include <cuda_runtime.h>

// SMFNet: out[i,:] = relu(X@Wf^T)[i,0]*V[i,:] + [i,1]*V[(i+1)%N,:],  V = relu(X@Wg^T)
// Thread-per-row via smem staging: no cross-lane reductions.

#define THREADS 128
#define TILE    128
#define RV      33                      // row stride in float4 (32 + 1 pad)
#define SX_F4   ((TILE + 1) * RV)       // 129 * 33 = 4257 float4
#define SW_F4   128                     // wf0,wf1,wg0,wg1 (32 float4 each)
#define SMEM_BYTES ((SX_F4 + SW_F4) * 16 + (TILE + 2) * 8)

__global__ void __launch_bounds__(THREADS)
smfnet_kernel(const float4* __restrict__ X,
              const float4* __restrict__ Wf,
              const float4* __restrict__ Wg,
              float2* __restrict__ out, int N)
{
    extern __shared__ float4 sm[];
    float4* sX = sm;                         // [TILE+1][RV]
    float4* sW = sm + SX_F4;                 // [128]
    float2* sV = (float2*)(sW + SW_F4);      // [TILE+1]

    const int t = threadIdx.x;
    const long long r0 = (long long)blockIdx.x * TILE;
    const int nrows = (int)min((long long)TILE, (long long)N - r0);

    // Stage weights (2 KB): sW[0..63]=Wf rows 0,1 ; sW[64..127]=Wg rows 0,1
    if (t < 64)  sW[t] = Wf[t];
    else         sW[t] = Wg[t - 64];

    // Stage X rows [r0, r0+nrows) plus wrapped boundary row (r0+nrows)%N.
    const int total = (nrows + 1) * 32;
    for (int idx = t; idx < total; idx += THREADS) {
        const int r = idx >> 5, c = idx & 31;
        long long g = r0 + r;
        if (r == nrows) g = (r0 + nrows) % (long long)N;
        sX[r * RV + c] = X[g * 32 + c];
    }
    __syncthreads();

    float f0 = 0.f, f1 = 0.f;
    if (t < nrows) {
        float g0 = 0.f, g1 = 0.f;
        const float4* xr = sX + t * RV;
        #pragma unroll 4
        for (int j = 0; j < 32; j++) {
            const float4 x = xr[j];
            const float4 a = sW[j];
            const float4 b = sW[32 + j];
            const float4 c = sW[64 + j];
            const float4 d = sW[96 + j];
            f0 = fmaf(x.x, a.x, fmaf(x.y, a.y, fmaf(x.z, a.z, fmaf(x.w, a.w, f0))));
            f1 = fmaf(x.x, b.x, fmaf(x.y, b.y, fmaf(x.z, b.z, fmaf(x.w, b.w, f1))));
            g0 = fmaf(x.x, c.x, fmaf(x.y, c.y, fmaf(x.z, c.z, fmaf(x.w, c.w, g0))));
            g1 = fmaf(x.x, d.x, fmaf(x.y, d.y, fmaf(x.z, d.z, fmaf(x.w, d.w, g1))));
        }
        f0 = fmaxf(f0, 0.f);
        f1 = fmaxf(f1, 0.f);
        sV[t] = make_float2(fmaxf(g0, 0.f), fmaxf(g1, 0.f));

        if (t == nrows - 1) {
            // Wrapped boundary row: only V (Wg dots) needed.
            float e0 = 0.f, e1 = 0.f;
            const float4* xe = sX + nrows * RV;
            #pragma unroll 4
            for (int j = 0; j < 32; j++) {
                const float4 x = xe[j];
                const float4 c = sW[64 + j];
                const float4 d = sW[96 + j];
                e0 = fmaf(x.x, c.x, fmaf(x.y, c.y, fmaf(x.z, c.z, fmaf(x.w, c.w, e0))));
                e1 = fmaf(x.x, d.x, fmaf(x.y, d.y, fmaf(x.z, d.z, fmaf(x.w, d.w, e1))));
            }
            sV[nrows] = make_float2(fmaxf(e0, 0.f), fmaxf(e1, 0.f));
        }
    }
    __syncthreads();

    if (t < nrows) {
        const float2 v  = sV[t];
        const float2 vn = sV[t + 1];
        out[r0 + t] = make_float2(fmaf(f0, v.x, f1 * vn.x),
                                  fmaf(f0, v.y, f1 * vn.y));
    }
}

extern "C" void kernel_launch(void* const* d_in, const int* in_sizes, int n_in,
                              void* d_out, int out_size) {
    const float4* X  = (const float4*)d_in[0];   // [N,128] fp32
    const float4* Wf = (const float4*)d_in[1];   // [2,128] fp32
    const float4* Wg = (const float4*)d_in[2];   // [2,128] fp32
    float2* out = (float2*)d_out;                // [N,2] fp32

    const int N = in_sizes[0] / 128;
    const int grid = (N + TILE - 1) / TILE;

    static bool attr_set = false;
    if (!attr_set) {
        cudaFuncSetAttribute(smfnet_kernel,
                             cudaFuncAttributeMaxDynamicSharedMemorySize,
                             SMEM_BYTES);
        attr_set = true;
    }

    smfnet_kernel<<<grid, THREADS, SMEM_BYTES>>>(X, Wf, Wg, out, N);
}